// round 4
// baseline (speedup 1.0000x reference)
#include <cuda_runtime.h>

#define BB 4
#define MM 128
#define LL 512
#define DD 768

#define NEGV   (-1e30f)
#define LSPLIT 6
#define LMAX   86
#define APAD   132     // sh_a row stride (floats): STS bank-clean (4l+m), LDS.128-aligned

// partial results [LSPLIT][B][M][D] = 9.4 MB static scratch
__device__ float g_scratch[LSPLIT * BB * MM * DD];

#define SMEM_FLOATS (LMAX * 128 + LMAX * APAD)
#define SMEM_BYTES  (SMEM_FLOATS * (int)sizeof(float))   // ~89.4 KB

__global__ __launch_bounds__(512, 1)
void mr_main(const float* __restrict__ h, const int* __restrict__ mask)
{
    extern __shared__ float smem[];
    float4* sh_h = (float4*)smem;            // [l][32] float4  (128 d)
    float*  sh_a = smem + LMAX * 128;        // [l][APAD] additive mask

    const int b    = blockIdx.z;
    const int d0   = blockIdx.x * 128;
    const int sp   = blockIdx.y;
    const int l0   = sp * 85 + (sp < 2 ? sp : 2);
    const int llen = 85 + (sp < 2 ? 1 : 0);

    const int tid  = threadIdx.x;
    const int lane = tid & 31;
    const int w    = tid >> 5;               // 16 warps; warp w -> m rows [w*8, w*8+8)

    // ---- stage h tile [llen][128] (coalesced float4) ----
    {
        const float4* hg = (const float4*)h + ((size_t)b * LL + l0) * (DD / 4) + (d0 >> 2);
        const int nf4 = llen * 32;
        for (int idx = tid; idx < nf4; idx += 512) {
            const int l = idx >> 5, q = idx & 31;
            sh_h[l * 32 + q] = hg[(size_t)l * (DD / 4) + q];
        }
    }
    // ---- stage additive mask transposed [l][m] (bank-conflict-free STS) ----
    {
        const int m = tid & 127;
        const int* mg = mask + ((size_t)b * MM + m) * LL + l0;
        for (int l = tid >> 7; l < llen; l += 4)
            sh_a[l * APAD + m] = mg[l] ? 0.0f : NEGV;
    }
    __syncthreads();

    // ---- accumulate: 8 m x 128 d per warp ----
    float4 acc[8];
#pragma unroll
    for (int i = 0; i < 8; ++i)
        acc[i] = make_float4(NEGV, NEGV, NEGV, NEGV);

    const int mb = w * 8;
#pragma unroll 2
    for (int l = 0; l < llen; ++l) {
        const float4 hv = sh_h[l * 32 + lane];
        const float* ar = sh_a + l * APAD + mb;     // uniform addr -> broadcast
        const float4 a0 = *(const float4*)ar;
        const float4 a1 = *(const float4*)(ar + 4);
        float a[8];
        a[0] = a0.x; a[1] = a0.y; a[2] = a0.z; a[3] = a0.w;
        a[4] = a1.x; a[5] = a1.y; a[6] = a1.z; a[7] = a1.w;
#pragma unroll
        for (int i = 0; i < 8; ++i) {
            acc[i].x = fmaxf(acc[i].x, hv.x + a[i]);
            acc[i].y = fmaxf(acc[i].y, hv.y + a[i]);
            acc[i].z = fmaxf(acc[i].z, hv.z + a[i]);
            acc[i].w = fmaxf(acc[i].w, hv.w + a[i]);
        }
    }

    // ---- write partials [sp][b][m][d] (coalesced float4) ----
    float* op = g_scratch + (((size_t)sp * BB + b) * MM + mb) * DD + d0 + lane * 4;
#pragma unroll
    for (int i = 0; i < 8; ++i)
        *(float4*)(op + (size_t)i * DD) = acc[i];
}

#define TOT4 (BB * MM * DD / 4)     // 98304 float4 outputs

__global__ __launch_bounds__(256, 1)
void mr_combine(float* __restrict__ out)
{
    const int t = blockIdx.x * 256 + threadIdx.x;    // 0..98303
    const float4* s = (const float4*)g_scratch;

    // 6 independent upfront loads -> MLP 6 per thread
    const float4 v0 = s[t];
    const float4 v1 = s[t + (size_t)1 * TOT4];
    const float4 v2 = s[t + (size_t)2 * TOT4];
    const float4 v3 = s[t + (size_t)3 * TOT4];
    const float4 v4 = s[t + (size_t)4 * TOT4];
    const float4 v5 = s[t + (size_t)5 * TOT4];

    float4 r;
    r.x = fmaxf(fmaxf(fmaxf(v0.x, v1.x), fmaxf(v2.x, v3.x)), fmaxf(v4.x, v5.x));
    r.y = fmaxf(fmaxf(fmaxf(v0.y, v1.y), fmaxf(v2.y, v3.y)), fmaxf(v4.y, v5.y));
    r.z = fmaxf(fmaxf(fmaxf(v0.z, v1.z), fmaxf(v2.z, v3.z)), fmaxf(v4.z, v5.z));
    r.w = fmaxf(fmaxf(fmaxf(v0.w, v1.w), fmaxf(v2.w, v3.w)), fmaxf(v4.w, v5.w));

    ((float4*)out)[t] = r;
}

extern "C" void kernel_launch(void* const* d_in, const int* in_sizes, int n_in,
                              void* d_out, int out_size)
{
    const float* h    = (const float*)d_in[0];
    const int*   mask = (const int*)  d_in[1];
    float*       out  = (float*)d_out;

    cudaFuncSetAttribute(mr_main,
                         cudaFuncAttributeMaxDynamicSharedMemorySize, SMEM_BYTES);

    dim3 grid(DD / 128, LSPLIT, BB);   // 6 x 6 x 4 = 144 blocks, 512 thr
    mr_main<<<grid, 512, SMEM_BYTES>>>(h, mask);
    mr_combine<<<TOT4 / 256, 256>>>(out);   // 384 blocks
}

// round 5
// speedup vs baseline: 1.5524x; 1.5524x over previous
#include <cuda_runtime.h>
#include <cuda_fp16.h>

#define BB 4
#define MM 128
#define LL 512
#define DD 768

#define LSPLIT 6
#define LMAX   86
#define APADU  132          // u32 row stride for sh_a ( *4B %16 == 0 -> LDS.128 aligned )
#define NEGH   0xFC00FC00u  // fp16x2 (-inf, -inf)

// fp16 partials [LSPLIT][B][M][D] = 4.7 MB static scratch (no allocs)
__device__ unsigned short g_scratch[LSPLIT * BB * MM * DD];

#define SH_H_U32   (LMAX * 64)
#define SMEM_BYTES ((SH_H_U32 + LMAX * APADU) * (int)sizeof(unsigned int))   // ~66 KB

__global__ __launch_bounds__(512, 1)
void mr_main(const float* __restrict__ h, const int* __restrict__ mask)
{
    extern __shared__ unsigned int sm[];
    unsigned int* sh_h = sm;              // [l][64] fp16x2  (128 d as 64 half2)
    unsigned int* sh_a = sm + SH_H_U32;   // [l][APADU] additive splat (0 or -inf,-inf)

    const int b    = blockIdx.z;
    const int d0   = blockIdx.x * 128;
    const int sp   = blockIdx.y;
    const int l0   = sp * 85 + (sp < 2 ? sp : 2);
    const int llen = 85 + (sp < 2 ? 1 : 0);

    const int tid  = threadIdx.x;
    const int lane = tid & 31;
    const int w    = tid >> 5;            // 16 warps; warp w -> m rows [8w, 8w+8)

    // ---- stage h tile: coalesced float4 LDG -> cvt fp16x2 -> STS ----
    {
        const float4* hg = (const float4*)h + ((size_t)b * LL + l0) * (DD / 4) + (d0 >> 2);
        const int n = llen * 32;
        for (int idx = tid; idx < n; idx += 512) {
            const int l = idx >> 5, q = idx & 31;
            const float4 v = hg[(size_t)l * (DD / 4) + q];
            const half2 p0 = __float22half2_rn(make_float2(v.x, v.y));
            const half2 p1 = __float22half2_rn(make_float2(v.z, v.w));
            sh_h[l * 64 + q * 2]     = *(const unsigned int*)&p0;
            sh_h[l * 64 + q * 2 + 1] = *(const unsigned int*)&p1;
        }
    }
    // ---- stage additive mask transposed [l][m]: LDG coalesced over l (lane=l) ----
    for (int m = w; m < MM; m += 16) {
        const int* mg = mask + ((size_t)b * MM + m) * LL + l0;
        for (int lb = lane; lb < llen; lb += 32)
            sh_a[lb * APADU + m] = mg[lb] ? 0u : NEGH;
    }
    __syncthreads();

    // ---- accumulate: 8 m x 128 d (fp16) per warp ----
    const unsigned int ninf = NEGH;
    const half2 hninf = *(const half2*)&ninf;
    half2 acc[8][2];
#pragma unroll
    for (int i = 0; i < 8; ++i) { acc[i][0] = hninf; acc[i][1] = hninf; }

    const int mb = w * 8;
#pragma unroll 2
    for (int l = 0; l < llen; ++l) {
        const uint2 hv = *(const uint2*)&sh_h[l * 64 + lane * 2];   // 4 d els
        const half2 h0 = *(const half2*)&hv.x;
        const half2 h1 = *(const half2*)&hv.y;
        const uint4 a0 = *(const uint4*)&sh_a[l * APADU + mb];      // uniform -> broadcast
        const uint4 a1 = *(const uint4*)&sh_a[l * APADU + mb + 4];
        unsigned int av[8] = {a0.x, a0.y, a0.z, a0.w, a1.x, a1.y, a1.z, a1.w};
#pragma unroll
        for (int i = 0; i < 8; ++i) {
            const half2 a = *(const half2*)&av[i];
            acc[i][0] = __hmax2(acc[i][0], __hadd2(h0, a));
            acc[i][1] = __hmax2(acc[i][1], __hadd2(h1, a));
        }
    }

    // ---- write fp16 partials [sp][b][m][d], coalesced 8B/thread ----
    unsigned short* op = g_scratch + (((size_t)sp * BB + b) * MM + mb) * DD + d0 + lane * 4;
#pragma unroll
    for (int i = 0; i < 8; ++i) {
        uint2 o;
        o.x = *(const unsigned int*)&acc[i][0];
        o.y = *(const unsigned int*)&acc[i][1];
        *(uint2*)(op + (size_t)i * DD) = o;
    }
}

#define TOTU2 (BB * MM * DD / 4)    // 98304 uint2 (4 fp16 each)

__global__ __launch_bounds__(256, 1)
void mr_combine(float* __restrict__ out)
{
    const int t = blockIdx.x * 256 + threadIdx.x;    // 0..98303
    const uint2* s = (const uint2*)g_scratch;

    uint2 v[LSPLIT];
#pragma unroll
    for (int sp = 0; sp < LSPLIT; ++sp)              // MLP 6
        v[sp] = s[(size_t)sp * TOTU2 + t];

    half2 r0 = *(const half2*)&v[0].x;
    half2 r1 = *(const half2*)&v[0].y;
#pragma unroll
    for (int sp = 1; sp < LSPLIT; ++sp) {
        r0 = __hmax2(r0, *(const half2*)&v[sp].x);
        r1 = __hmax2(r1, *(const half2*)&v[sp].y);
    }
    const float2 f0 = __half22float2(r0);
    const float2 f1 = __half22float2(r1);
    float4 o; o.x = f0.x; o.y = f0.y; o.z = f1.x; o.w = f1.y;
    ((float4*)out)[t] = o;
}

extern "C" void kernel_launch(void* const* d_in, const int* in_sizes, int n_in,
                              void* d_out, int out_size)
{
    const float* h    = (const float*)d_in[0];
    const int*   mask = (const int*)  d_in[1];
    float*       out  = (float*)d_out;

    cudaFuncSetAttribute(mr_main,
                         cudaFuncAttributeMaxDynamicSharedMemorySize, SMEM_BYTES);

    dim3 grid(DD / 128, LSPLIT, BB);      // 6 x 6 x 4 = 144 blocks
    mr_main<<<grid, 512, SMEM_BYTES>>>(h, mask);
    mr_combine<<<TOTU2 / 256, 256>>>(out);   // 384 blocks
}